// round 9
// baseline (speedup 1.0000x reference)
#include <cuda_runtime.h>
#include <cuda_fp16.h>
#include <math.h>

#define SVAL 64
#define DIM 256
#define PD 260                    // padded dim: xi/yi/zi in [0,259], data at [2,257]
#define PD2 (PD * PD)             // 67600
#define PVOX (PD * PD * PD)       // 17.576M entries * 4B = 70.3MB (< L2 126MB)
#define GROUPS_PER_ROW (PD / 4)   // 65 uint4 groups per row

// Zero-padded x-pair-duplicated half2 volume.
// Entry (xi,yi,zi) with x0=xi-2, y=yi-2, z=zi-2:
//   (vget(x0), vget(x0+1)) at row (y,z); vget OOB -> 0; skirt rows all-zero.
__device__ __half2 g_pad[PVOX];

// Fat-thread builder: one thread = one uint4 (4 entries). No smem, no syncs.
__global__ __launch_bounds__(256) void build_pad_kernel(const float* __restrict__ vol)
{
    const int t = blockIdx.x * blockDim.x + threadIdx.x;
    if (t >= PD2 * GROUPS_PER_ROW) return;

    const int row = t / GROUPS_PER_ROW;          // (zi,yi) row id
    const int g   = t - row * GROUPS_PER_ROW;    // group along x
    const int zi  = row / PD;
    const int yi  = row - zi * PD;
    const int z = zi - 2, y = yi - 2;

    uint4* outp = (uint4*)((unsigned*)g_pad + (size_t)row * PD) + g;

    const bool real = ((unsigned)z < 256u) & ((unsigned)y < 256u);
    if (!real) {
        *outp = make_uint4(0u, 0u, 0u, 0u);
        return;
    }

    const float4* vrow4 = (const float4*)(vol + ((size_t)z * DIM + y) * DIM);
    const float4 Z4 = make_float4(0.f, 0.f, 0.f, 0.f);
    // vals[j] = v[4g-4+j], j=0..7 (OOB -> 0)
    const float4 A = (g >= 1) ? __ldg(vrow4 + (g - 1)) : Z4;                 // x = 4g-4..4g-1
    const float4 B = (g <= (DIM / 4) - 1) ? __ldg(vrow4 + g) : Z4;           // x = 4g..4g+3

    const float vals[8] = { A.x, A.y, A.z, A.w, B.x, B.y, B.z, B.w };

    uint4 o;
    {   // entry k: x0 = 4g-2+k -> lo=vals[2+k], hi=vals[3+k]
        __half2 h0 = __floats2half2_rn(vals[2], vals[3]);
        __half2 h1 = __floats2half2_rn(vals[3], vals[4]);
        __half2 h2 = __floats2half2_rn(vals[4], vals[5]);
        __half2 h3 = __floats2half2_rn(vals[5], vals[6]);
        o.x = *(unsigned*)&h0;
        o.y = *(unsigned*)&h1;
        o.z = *(unsigned*)&h2;
        o.w = *(unsigned*)&h3;
    }
    *outp = o;
}

__global__ __launch_bounds__(256) void psf_sample_kernel(
    const float* __restrict__ sampleGrid, // [N,3]
    const float* __restrict__ ax,         // [N,6]
    const float* __restrict__ bound,      // [N,2,3]
    const float* __restrict__ invcov,     // [3,3]
    const float* __restrict__ xyz_psf,    // [N,S,3]
    float* __restrict__ out,              // [N]
    int N)
{
    const int warps_per_block = blockDim.x >> 5;
    const int n = blockIdx.x * warps_per_block + (threadIdx.x >> 5);
    if (n >= N) return;
    const int lane = threadIdx.x & 31;

    // ---- per-ray uniform setup (broadcast loads) ----
    const float vx = __ldg(ax + (size_t)n * 6 + 0);
    const float vy = __ldg(ax + (size_t)n * 6 + 1);
    const float vz = __ldg(ax + (size_t)n * 6 + 2);
    const float tx = __ldg(ax + (size_t)n * 6 + 3);
    const float ty = __ldg(ax + (size_t)n * 6 + 4);
    const float tz = __ldg(ax + (size_t)n * 6 + 5);

    const float theta = sqrtf(vx * vx + vy * vy + vz * vz);
    const float invt = 1.0f / fmaxf(theta, 1e-12f);
    const float kx = vx * invt, ky = vy * invt, kz = vz * invt;
    const float st = sinf(theta);
    const float ct = cosf(theta);
    const float oc = 1.0f - ct;

    const float r00 = 1.0f - oc * (ky * ky + kz * kz);
    const float r01 = -st * kz + oc * kx * ky;
    const float r02 =  st * ky + oc * kx * kz;
    const float r10 =  st * kz + oc * kx * ky;
    const float r11 = 1.0f - oc * (kx * kx + kz * kz);
    const float r12 = -st * kx + oc * ky * kz;
    const float r20 = -st * ky + oc * kx * kz;
    const float r21 =  st * kx + oc * ky * kz;
    const float r22 = 1.0f - oc * (kx * kx + ky * ky);

    const float sgx = __ldg(sampleGrid + (size_t)n * 3 + 0);
    const float sgy = __ldg(sampleGrid + (size_t)n * 3 + 1);
    const float sgz = __ldg(sampleGrid + (size_t)n * 3 + 2);

    const float px = sgx + tx, py = sgy + ty, pz = sgz + tz;
    const float cx = r00 * px + r01 * py + r02 * pz;
    const float cy = r10 * px + r11 * py + r12 * pz;
    const float cz = r20 * px + r21 * py + r22 * pz;

    const float hx = 0.5f * (__ldg(bound + (size_t)n * 6 + 3) - __ldg(bound + (size_t)n * 6 + 0));
    const float hy = 0.5f * (__ldg(bound + (size_t)n * 6 + 4) - __ldg(bound + (size_t)n * 6 + 1));
    const float hz = 0.5f * (__ldg(bound + (size_t)n * 6 + 5) - __ldg(bound + (size_t)n * 6 + 2));

    const float c00 = __ldg(invcov + 0), c01 = __ldg(invcov + 1), c02 = __ldg(invcov + 2);
    const float c10 = __ldg(invcov + 3), c11 = __ldg(invcov + 4), c12 = __ldg(invcov + 5);
    const float c20 = __ldg(invcov + 6), c21 = __ldg(invcov + 7), c22 = __ldg(invcov + 8);

    float sum_vw = 0.0f;
    float sum_w = 0.0f;

    const float* psf_base = xyz_psf + (size_t)n * SVAL * 3;
    const float SCL = 256.0f / 255.0f;   // pix = world*SCL - 0.5

#pragma unroll
    for (int rep = 0; rep < 2; rep++) {
        const int s = lane + rep * 32;
        // evict-first: one-shot 100MB stream must not displace the L2-resident volume
        const float ex = __ldcs(psf_base + s * 3 + 0) * hx;
        const float ey = __ldcs(psf_base + s * 3 + 1) * hy;
        const float ez = __ldcs(psf_base + s * 3 + 2) * hz;

        const float pixx = fmaf(cx + ex, SCL, -0.5f);
        const float pixy = fmaf(cy + ey, SCL, -0.5f);
        const float pixz = fmaf(cz + ez, SCL, -0.5f);

        const float fx0 = floorf(pixx), fy0 = floorf(pixy), fz0 = floorf(pixz);
        const int x0 = (int)fx0, y0 = (int)fy0, z0 = (int)fz0;
        const float fx = pixx - fx0, fy = pixy - fy0, fz = pixz - fz0;

        // padded indices; all OOB cases land in the zero skirt
        const int xi = min(max(x0 + 2, 0), PD - 2);
        const int yi = min(max(y0 + 2, 0), PD - 2);
        const int zi = min(max(z0 + 2, 0), PD - 2);

        const int b = (zi * PD + yi) * PD + xi;

        const float2 f00 = __half22float2(__ldg(g_pad + b));
        const float2 f01 = __half22float2(__ldg(g_pad + b + PD));
        const float2 f10 = __half22float2(__ldg(g_pad + b + PD2));
        const float2 f11 = __half22float2(__ldg(g_pad + b + PD2 + PD));

        const float xi00 = fmaf(fx, f00.y - f00.x, f00.x);
        const float xi01 = fmaf(fx, f01.y - f01.x, f01.x);
        const float xi10 = fmaf(fx, f10.y - f10.x, f10.x);
        const float xi11 = fmaf(fx, f11.y - f11.x, f11.x);
        const float yi0 = fmaf(fy, xi01 - xi00, xi00);
        const float yi1 = fmaf(fy, xi11 - xi10, xi10);
        const float val = fmaf(fz, yi1 - yi0, yi0);

        const float q =
            ex * (c00 * ex + c01 * ey + c02 * ez) +
            ey * (c10 * ex + c11 * ey + c12 * ez) +
            ez * (c20 * ex + c21 * ey + c22 * ez);
        const float w = __expf(-0.5f * q);

        sum_vw = fmaf(w, val, sum_vw);
        sum_w += w;
    }

#pragma unroll
    for (int off = 16; off > 0; off >>= 1) {
        sum_vw += __shfl_xor_sync(0xFFFFFFFFu, sum_vw, off);
        sum_w  += __shfl_xor_sync(0xFFFFFFFFu, sum_w, off);
    }

    if (lane == 0) {
        out[n] = sum_vw / sum_w;
    }
}

extern "C" void kernel_launch(void* const* d_in, const int* in_sizes, int n_in,
                              void* d_out, int out_size)
{
    const float* x          = (const float*)d_in[0];
    const float* sampleGrid = (const float*)d_in[1];
    const float* ax         = (const float*)d_in[2];
    const float* bound      = (const float*)d_in[3];
    const float* invcov     = (const float*)d_in[4];
    const float* xyz_psf    = (const float*)d_in[5];
    float* out = (float*)d_out;

    const int N = in_sizes[1] / 3;

    // Pre-pass: build zero-padded x-dup half2 volume (70.3MB, L2-resident)
    {
        const int total = PD2 * GROUPS_PER_ROW;
        const int threads = 256;
        const int blocks = (total + threads - 1) / threads;
        build_pad_kernel<<<blocks, threads>>>(x);
    }

    // Main kernel: warp per ray
    {
        const int threads = 256;
        const int warps_per_block = threads / 32;
        const int blocks = (N + warps_per_block - 1) / warps_per_block;
        psf_sample_kernel<<<blocks, threads>>>(sampleGrid, ax, bound, invcov,
                                               xyz_psf, out, N);
    }
}

// round 11
// speedup vs baseline: 1.4720x; 1.4720x over previous
#include <cuda_runtime.h>
#include <cuda_fp16.h>
#include <math.h>

#define SVAL 64
#define DIM 256
#define PD 260                    // padded dim: xi/yi/zi in [0,259], data at [2,257]
#define PD2 (PD * PD)             // 67600
#define PVOX (PD * PD * PD)       // 17.576M entries * 4B = 70.3MB (< L2 126MB)
#define GROUPS_PER_ROW (PD / 4)   // 65 uint4 groups per row

// Zero-padded x-pair-duplicated half2 volume.
// Entry (xi,yi,zi) with x0=xi-2, y=yi-2, z=zi-2:
//   (vget(x0), vget(x0+1)) at row (y,z); vget OOB -> 0; skirt rows all-zero.
__device__ __half2 g_pad[PVOX];

// L2-evict-first via cache policy (sm_103a requires the cache_hint form for
// scalar loads). L1 policy stays default (R9 lesson: L1 evict-first breaks
// overlapping-line reuse among the strided psf loads).
__device__ __forceinline__ float ld_l2ef(const float* p)
{
    float v;
    asm volatile(
        "{\n\t"
        ".reg .b64 pol;\n\t"
        "createpolicy.fractional.L2::evict_first.b64 pol, 1.0;\n\t"
        "ld.global.L2::cache_hint.f32 %0, [%1], pol;\n\t"
        "}"
        : "=f"(v) : "l"(p));
    return v;
}

// Fat-thread builder: one thread = one uint4 (4 entries). No smem, no syncs.
__global__ __launch_bounds__(256) void build_pad_kernel(const float* __restrict__ vol)
{
    const int t = blockIdx.x * blockDim.x + threadIdx.x;
    if (t >= PD2 * GROUPS_PER_ROW) return;

    const int row = t / GROUPS_PER_ROW;          // (zi,yi) row id
    const int g   = t - row * GROUPS_PER_ROW;    // group along x
    const int zi  = row / PD;
    const int yi  = row - zi * PD;
    const int z = zi - 2, y = yi - 2;

    uint4* outp = (uint4*)((unsigned*)g_pad + (size_t)row * PD) + g;

    const bool real = ((unsigned)z < 256u) & ((unsigned)y < 256u);
    if (!real) {
        *outp = make_uint4(0u, 0u, 0u, 0u);
        return;
    }

    const float4* vrow4 = (const float4*)(vol + ((size_t)z * DIM + y) * DIM);
    const float4 Z4 = make_float4(0.f, 0.f, 0.f, 0.f);
    // vals[j] = v[4g-4+j], j=0..7 (OOB -> 0)
    const float4 A = (g >= 1) ? __ldg(vrow4 + (g - 1)) : Z4;
    const float4 B = (g <= (DIM / 4) - 1) ? __ldg(vrow4 + g) : Z4;

    const float vals[8] = { A.x, A.y, A.z, A.w, B.x, B.y, B.z, B.w };

    uint4 o;
    {   // entry k: x0 = 4g-2+k -> lo=vals[2+k], hi=vals[3+k]
        __half2 h0 = __floats2half2_rn(vals[2], vals[3]);
        __half2 h1 = __floats2half2_rn(vals[3], vals[4]);
        __half2 h2 = __floats2half2_rn(vals[4], vals[5]);
        __half2 h3 = __floats2half2_rn(vals[5], vals[6]);
        o.x = *(unsigned*)&h0;
        o.y = *(unsigned*)&h1;
        o.z = *(unsigned*)&h2;
        o.w = *(unsigned*)&h3;
    }
    *outp = o;
}

__global__ __launch_bounds__(256) void psf_sample_kernel(
    const float* __restrict__ sampleGrid, // [N,3]
    const float* __restrict__ ax,         // [N,6]
    const float* __restrict__ bound,      // [N,2,3]
    const float* __restrict__ invcov,     // [3,3]
    const float* __restrict__ xyz_psf,    // [N,S,3]
    float* __restrict__ out,              // [N]
    int N)
{
    const int warps_per_block = blockDim.x >> 5;
    const int n = blockIdx.x * warps_per_block + (threadIdx.x >> 5);
    if (n >= N) return;
    const int lane = threadIdx.x & 31;

    // ---- hoist psf loads: DRAM latency overlaps all the setup math below ----
    const float* psf_base = xyz_psf + (size_t)n * SVAL * 3;
    float pe[2][3];
#pragma unroll
    for (int rep = 0; rep < 2; rep++) {
        const int s = lane + rep * 32;
        pe[rep][0] = ld_l2ef(psf_base + s * 3 + 0);
        pe[rep][1] = ld_l2ef(psf_base + s * 3 + 1);
        pe[rep][2] = ld_l2ef(psf_base + s * 3 + 2);
    }

    // ---- per-ray uniform setup (broadcast loads) ----
    const float vx = __ldg(ax + (size_t)n * 6 + 0);
    const float vy = __ldg(ax + (size_t)n * 6 + 1);
    const float vz = __ldg(ax + (size_t)n * 6 + 2);
    const float tx = __ldg(ax + (size_t)n * 6 + 3);
    const float ty = __ldg(ax + (size_t)n * 6 + 4);
    const float tz = __ldg(ax + (size_t)n * 6 + 5);

    const float theta = sqrtf(vx * vx + vy * vy + vz * vz);
    const float invt = 1.0f / fmaxf(theta, 1e-12f);
    const float kx = vx * invt, ky = vy * invt, kz = vz * invt;
    const float st = sinf(theta);
    const float ct = cosf(theta);
    const float oc = 1.0f - ct;

    const float r00 = 1.0f - oc * (ky * ky + kz * kz);
    const float r01 = -st * kz + oc * kx * ky;
    const float r02 =  st * ky + oc * kx * kz;
    const float r10 =  st * kz + oc * kx * ky;
    const float r11 = 1.0f - oc * (kx * kx + kz * kz);
    const float r12 = -st * kx + oc * ky * kz;
    const float r20 = -st * ky + oc * kx * kz;
    const float r21 =  st * kx + oc * ky * kz;
    const float r22 = 1.0f - oc * (kx * kx + ky * ky);

    const float sgx = __ldg(sampleGrid + (size_t)n * 3 + 0);
    const float sgy = __ldg(sampleGrid + (size_t)n * 3 + 1);
    const float sgz = __ldg(sampleGrid + (size_t)n * 3 + 2);

    const float px = sgx + tx, py = sgy + ty, pz = sgz + tz;
    const float cx = r00 * px + r01 * py + r02 * pz;
    const float cy = r10 * px + r11 * py + r12 * pz;
    const float cz = r20 * px + r21 * py + r22 * pz;

    const float hx = 0.5f * (__ldg(bound + (size_t)n * 6 + 3) - __ldg(bound + (size_t)n * 6 + 0));
    const float hy = 0.5f * (__ldg(bound + (size_t)n * 6 + 4) - __ldg(bound + (size_t)n * 6 + 1));
    const float hz = 0.5f * (__ldg(bound + (size_t)n * 6 + 5) - __ldg(bound + (size_t)n * 6 + 2));

    const float c00 = __ldg(invcov + 0), c01 = __ldg(invcov + 1), c02 = __ldg(invcov + 2);
    const float c10 = __ldg(invcov + 3), c11 = __ldg(invcov + 4), c12 = __ldg(invcov + 5);
    const float c20 = __ldg(invcov + 6), c21 = __ldg(invcov + 7), c22 = __ldg(invcov + 8);

    float sum_vw = 0.0f;
    float sum_w = 0.0f;

    const float SCL = 256.0f / 255.0f;   // pix = world*SCL - 0.5

#pragma unroll
    for (int rep = 0; rep < 2; rep++) {
        const float ex = pe[rep][0] * hx;
        const float ey = pe[rep][1] * hy;
        const float ez = pe[rep][2] * hz;

        const float pixx = fmaf(cx + ex, SCL, -0.5f);
        const float pixy = fmaf(cy + ey, SCL, -0.5f);
        const float pixz = fmaf(cz + ez, SCL, -0.5f);

        const float fx0 = floorf(pixx), fy0 = floorf(pixy), fz0 = floorf(pixz);
        const int x0 = (int)fx0, y0 = (int)fy0, z0 = (int)fz0;
        const float fx = pixx - fx0, fy = pixy - fy0, fz = pixz - fz0;

        // padded indices; all OOB cases land in the zero skirt
        const int xi = min(max(x0 + 2, 0), PD - 2);
        const int yi = min(max(y0 + 2, 0), PD - 2);
        const int zi = min(max(z0 + 2, 0), PD - 2);

        const int b = (zi * PD + yi) * PD + xi;

        const float2 f00 = __half22float2(__ldg(g_pad + b));
        const float2 f01 = __half22float2(__ldg(g_pad + b + PD));
        const float2 f10 = __half22float2(__ldg(g_pad + b + PD2));
        const float2 f11 = __half22float2(__ldg(g_pad + b + PD2 + PD));

        const float xi00 = fmaf(fx, f00.y - f00.x, f00.x);
        const float xi01 = fmaf(fx, f01.y - f01.x, f01.x);
        const float xi10 = fmaf(fx, f10.y - f10.x, f10.x);
        const float xi11 = fmaf(fx, f11.y - f11.x, f11.x);
        const float yi0 = fmaf(fy, xi01 - xi00, xi00);
        const float yi1 = fmaf(fy, xi11 - xi10, xi10);
        const float val = fmaf(fz, yi1 - yi0, yi0);

        const float q =
            ex * (c00 * ex + c01 * ey + c02 * ez) +
            ey * (c10 * ex + c11 * ey + c12 * ez) +
            ez * (c20 * ex + c21 * ey + c22 * ez);
        const float w = __expf(-0.5f * q);

        sum_vw = fmaf(w, val, sum_vw);
        sum_w += w;
    }

#pragma unroll
    for (int off = 16; off > 0; off >>= 1) {
        sum_vw += __shfl_xor_sync(0xFFFFFFFFu, sum_vw, off);
        sum_w  += __shfl_xor_sync(0xFFFFFFFFu, sum_w, off);
    }

    if (lane == 0) {
        out[n] = sum_vw / sum_w;
    }
}

extern "C" void kernel_launch(void* const* d_in, const int* in_sizes, int n_in,
                              void* d_out, int out_size)
{
    const float* x          = (const float*)d_in[0];
    const float* sampleGrid = (const float*)d_in[1];
    const float* ax         = (const float*)d_in[2];
    const float* bound      = (const float*)d_in[3];
    const float* invcov     = (const float*)d_in[4];
    const float* xyz_psf    = (const float*)d_in[5];
    float* out = (float*)d_out;

    const int N = in_sizes[1] / 3;

    // Pre-pass: build zero-padded x-dup half2 volume (70.3MB, L2-resident)
    {
        const int total = PD2 * GROUPS_PER_ROW;
        const int threads = 256;
        const int blocks = (total + threads - 1) / threads;
        build_pad_kernel<<<blocks, threads>>>(x);
    }

    // Main kernel: warp per ray
    {
        const int threads = 256;
        const int warps_per_block = threads / 32;
        const int blocks = (N + warps_per_block - 1) / warps_per_block;
        psf_sample_kernel<<<blocks, threads>>>(sampleGrid, ax, bound, invcov,
                                               xyz_psf, out, N);
    }
}